// round 4
// baseline (speedup 1.0000x reference)
#include <cuda_runtime.h>
#include <math.h>

#define BB 2
#define HH 720
#define WW 1280
#define HW (HH*WW)
#define NPIX (BB*HW)
#define EPSF 1e-7f

// Scratch: splat accumulators [dir][b][pixel][4ch]  (~59 MB)
__device__ __align__(16) float g_acc[(size_t)2 * BB * HW * 4];

// ---------------------------------------------------------------------------
// Splat kernel: each thread handles one source pixel, both warp directions.
// sm_90+ float4 atomicAdd -> one RED.E.128 per corner.
// ---------------------------------------------------------------------------
__global__ void __launch_bounds__(256) splat_kernel(
    const float* __restrict__ img0, const float* __restrict__ img1,
    const float* __restrict__ flow0, const float* __restrict__ flow1,
    const float* __restrict__ z0, const float* __restrict__ z1)
{
    int i = blockIdx.x * blockDim.x + threadIdx.x;
    if (i >= NPIX) return;
    int b = i / HW;
    int p = i - b * HW;
    int y = p / WW;
    int x = p - y * WW;

#pragma unroll
    for (int d = 0; d < 2; ++d) {
        const float* img = d ? img1 : img0;
        const float* fl  = d ? flow0 : flow1;
        const float* zz  = d ? z0 : z1;

        float fx = (float)x + 0.5f * fl[(size_t)(b * 2 + 1) * HW + p];
        float fy = (float)y + 0.5f * fl[(size_t)(b * 2 + 0) * HW + p];
        float w  = __expf(zz[(size_t)b * HW + p]);
        float vr = img[(size_t)(b * 3 + 0) * HW + p] * w;
        float vg = img[(size_t)(b * 3 + 1) * HW + p] * w;
        float vb = img[(size_t)(b * 3 + 2) * HW + p] * w;

        float x0f = floorf(fx), y0f = floorf(fy);
        int ix0 = (int)x0f, iy0 = (int)y0f;
        float ax = fx - x0f, ay = fy - y0f;

        float4* acc = reinterpret_cast<float4*>(g_acc) + (size_t)(d * BB + b) * HW;
#pragma unroll
        for (int cy = 0; cy < 2; ++cy) {
            int ty = iy0 + cy;
            if ((unsigned)ty >= (unsigned)HH) continue;
            float wy = cy ? ay : (1.0f - ay);
#pragma unroll
            for (int cx = 0; cx < 2; ++cx) {
                int tx = ix0 + cx;
                if ((unsigned)tx >= (unsigned)WW) continue;
                float wt = wy * (cx ? ax : (1.0f - ax));
                atomicAdd(acc + ((size_t)ty * WW + tx),
                          make_float4(vr * wt, vg * wt, vb * wt, w * wt));
            }
        }
    }
}

// ---------------------------------------------------------------------------
// Fused normalize + morphological open + compose.
// Tile 64x16 pixels, block 16x16 threads, 4 px/thread (vector float4 I/O).
// Template-specialized on radius R; smem buffers overlaid across stages.
//   BufA: s_in  (stage 1-2)  then s_er (stage 3-4)
//   BufB: s_hm  (stage 2-3)  then s_hx (stage 4-5)
// ---------------------------------------------------------------------------
#define TPX 64          // tile width in pixels
#define TBX 16          // threads in x (4 px each)
#define TTY 16          // tile height / threads in y
#define RMAX 4
#define NT (TBX * TTY)  // 256 threads

#define BUFA_FLOATS (2 * (TPX + 4 * RMAX) * (TTY + 4 * RMAX))  // 2*80*32 = 5120
#define BUFB_FLOATS (2 * (TPX + 2 * RMAX) * (TTY + 4 * RMAX))  // 2*72*32 = 4608

template<int R>
__device__ __forceinline__ void open_body(
    float* __restrict__ BufA, float* __restrict__ BufB,
    const float* __restrict__ flow0, const float* __restrict__ flow1,
    float* __restrict__ out)
{
    constexpr int INW = TPX + 4 * R;
    constexpr int INH = TTY + 4 * R;
    constexpr int HMW = TPX + 2 * R;
    constexpr int EH  = TTY + 2 * R;
    constexpr int WIN = 2 * R;

    const float PINF = __int_as_float(0x7f800000);
    const float NINF = __int_as_float(0xff800000);

    int b  = blockIdx.z;
    int ox = blockIdx.x * TPX;
    int oy = blockIdx.y * TTY;
    int tid = threadIdx.y * TBX + threadIdx.x;

    // Stage 1: halo mask loads m = w/(w+eps); +inf outside image
#pragma unroll
    for (int m = 0; m < 2; ++m) {
        const float* wbase = g_acc + ((size_t)(m * BB + b) * HW << 2) + 3;
        float* s_in = BufA + m * INH * INW;
        for (int idx = tid; idx < INH * INW; idx += NT) {
            int iy = idx / INW;
            int ix = idx - iy * INW;
            int hy = oy - 2 * R + iy;
            int hx = ox - 2 * R + ix;
            float v = PINF;
            if ((unsigned)hy < (unsigned)HH && (unsigned)hx < (unsigned)WW) {
                float wv = wbase[((size_t)hy * WW + hx) << 2];
                v = wv / (wv + EPSF);
            }
            s_in[idx] = v;
        }
    }
    __syncthreads();

    // Stage 2: horizontal min (s_in -> s_hm)
#pragma unroll
    for (int m = 0; m < 2; ++m) {
        const float* s_in = BufA + m * INH * INW;
        float* s_hm = BufB + m * INH * HMW;
        for (int idx = tid; idx < INH * HMW; idx += NT) {
            int iy = idx / HMW;
            int hx = idx - iy * HMW;
            const float* row = s_in + iy * INW + hx;
            float v = row[0];
#pragma unroll
            for (int dd = 1; dd <= WIN; ++dd) v = fminf(v, row[dd]);
            s_hm[idx] = v;
        }
    }
    __syncthreads();

    // Stage 3: vertical min -> erosion (s_hm -> s_er); out-of-image -> -inf
#pragma unroll
    for (int m = 0; m < 2; ++m) {
        const float* s_hm = BufB + m * INH * HMW;
        float* s_er = BufA + m * EH * HMW;
        for (int idx = tid; idx < EH * HMW; idx += NT) {
            int ey = idx / HMW;
            int hx = idx - ey * HMW;
            int hy = oy - R + ey;
            int hgx = ox - R + hx;
            float v = NINF;
            if ((unsigned)hy < (unsigned)HH && (unsigned)hgx < (unsigned)WW) {
                const float* col = s_hm + ey * HMW + hx;
                v = col[0];
#pragma unroll
                for (int dd = 1; dd <= WIN; ++dd) v = fminf(v, col[dd * HMW]);
            }
            s_er[idx] = v;
        }
    }
    __syncthreads();

    // Stage 4: horizontal max (s_er -> s_hx)
#pragma unroll
    for (int m = 0; m < 2; ++m) {
        const float* s_er = BufA + m * EH * HMW;
        float* s_hx = BufB + m * EH * TPX;
        for (int idx = tid; idx < EH * TPX; idx += NT) {
            int ey = idx / TPX;
            int xx = idx - ey * TPX;
            const float* row = s_er + ey * HMW + xx;
            float v = row[0];
#pragma unroll
            for (int dd = 1; dd <= WIN; ++dd) v = fmaxf(v, row[dd]);
            s_hx[idx] = v;
        }
    }
    __syncthreads();

    // Stage 5: vertical max -> opened masks; normalize + compose, float4 I/O.
    // H,W divide tile exactly -> no center bounds checks needed.
    int txx = threadIdx.x, tyy = threadIdx.y;
    int gx0 = ox + txx * 4;
    int gy  = oy + tyy;
    size_t p = (size_t)gy * WW + gx0;

    float4 m01v, m10v;
    {
        const float* h0 = BufB + 0 * EH * TPX + tyy * TPX + txx * 4;
        const float* h1 = BufB + 1 * EH * TPX + tyy * TPX + txx * 4;
        float a[4], c[4];
#pragma unroll
        for (int j = 0; j < 4; ++j) { a[j] = h0[j]; c[j] = h1[j]; }
#pragma unroll
        for (int dd = 1; dd <= WIN; ++dd) {
#pragma unroll
            for (int j = 0; j < 4; ++j) {
                a[j] = fmaxf(a[j], h0[dd * TPX + j]);
                c[j] = fmaxf(c[j], h1[dd * TPX + j]);
            }
        }
        m01v = make_float4(a[0], a[1], a[2], a[3]);
        m10v = make_float4(c[0], c[1], c[2], c[3]);
    }

    // Normalized RGB for 4 pixels, both directions
    float4 f01[3], f10[3];  // [rgb].{x,y,z,w} = 4 pixels
    {
        const float4* acc0 = reinterpret_cast<const float4*>(g_acc) + (size_t)(0 * BB + b) * HW + p;
        const float4* acc1 = reinterpret_cast<const float4*>(g_acc) + (size_t)(1 * BB + b) * HW + p;
#pragma unroll
        for (int j = 0; j < 4; ++j) {
            float4 a0 = acc0[j];
            float4 a1 = acc1[j];
            float i0 = 1.0f / (a0.w + EPSF);
            float i1 = 1.0f / (a1.w + EPSF);
            ((float*)&f01[0])[j] = a0.x * i0;
            ((float*)&f01[1])[j] = a0.y * i0;
            ((float*)&f01[2])[j] = a0.z * i0;
            ((float*)&f10[0])[j] = a1.x * i1;
            ((float*)&f10[1])[j] = a1.y * i1;
            ((float*)&f10[2])[j] = a1.z * i1;
        }
    }

    float4* ob = reinterpret_cast<float4*>(out + (size_t)b * 18 * HW + p);
    const size_t S = HW / 4;  // float4 stride per channel
#define LERP4(mm, A, B) make_float4( \
        mm.x * A.x + (1.0f - mm.x) * B.x, \
        mm.y * A.y + (1.0f - mm.y) * B.y, \
        mm.z * A.z + (1.0f - mm.z) * B.z, \
        mm.w * A.w + (1.0f - mm.w) * B.w)
    ob[0 * S] = LERP4(m01v, f01[0], f10[0]);
    ob[1 * S] = LERP4(m01v, f01[1], f10[1]);
    ob[2 * S] = LERP4(m01v, f01[2], f10[2]);
    ob[3 * S] = LERP4(m10v, f10[0], f01[0]);
    ob[4 * S] = LERP4(m10v, f10[1], f01[1]);
    ob[5 * S] = LERP4(m10v, f10[2], f01[2]);
    ob[6 * S] = f01[0];
    ob[7 * S] = f01[1];
    ob[8 * S] = f01[2];
    ob[9 * S]  = f10[0];
    ob[10 * S] = f10[1];
    ob[11 * S] = f10[2];
#undef LERP4

    const float4* fl0 = reinterpret_cast<const float4*>(flow0 + (size_t)b * 2 * HW) ;
    const float4* fl1 = reinterpret_cast<const float4*>(flow1 + (size_t)b * 2 * HW);
    size_t p4 = p / 4;
    float4 q;
    q = fl0[0 * S + p4]; ob[12 * S] = make_float4(0.5f*q.x, 0.5f*q.y, 0.5f*q.z, 0.5f*q.w);
    q = fl0[1 * S + p4]; ob[13 * S] = make_float4(0.5f*q.x, 0.5f*q.y, 0.5f*q.z, 0.5f*q.w);
    q = fl1[0 * S + p4]; ob[14 * S] = make_float4(0.5f*q.x, 0.5f*q.y, 0.5f*q.z, 0.5f*q.w);
    q = fl1[1 * S + p4]; ob[15 * S] = make_float4(0.5f*q.x, 0.5f*q.y, 0.5f*q.z, 0.5f*q.w);
    ob[16 * S] = m01v;
    ob[17 * S] = m10v;
}

__global__ void __launch_bounds__(NT) open_compose_kernel(
    const int* __restrict__ kptr,
    const float* __restrict__ flow0, const float* __restrict__ flow1,
    float* __restrict__ out)
{
    __shared__ float BufA[BUFA_FLOATS];
    __shared__ float BufB[BUFB_FLOATS];

    int kk = kptr[0];
    int r = (kk >= 2) ? (kk - 1) / 2 : 0;
    if (r > RMAX) r = RMAX;

    switch (r) {
        case 0: open_body<0>(BufA, BufB, flow0, flow1, out); break;
        case 1: open_body<1>(BufA, BufB, flow0, flow1, out); break;
        case 2: open_body<2>(BufA, BufB, flow0, flow1, out); break;
        case 3: open_body<3>(BufA, BufB, flow0, flow1, out); break;
        default: open_body<4>(BufA, BufB, flow0, flow1, out); break;
    }
}

// ---------------------------------------------------------------------------
extern "C" void kernel_launch(void* const* d_in, const int* in_sizes, int n_in,
                              void* d_out, int out_size)
{
    const float* img0  = (const float*)d_in[0];
    const float* img1  = (const float*)d_in[1];
    const float* flow0 = (const float*)d_in[2];
    const float* flow1 = (const float*)d_in[3];
    const float* z0    = (const float*)d_in[4];
    const float* z1    = (const float*)d_in[5];
    const int*   kptr  = (const int*)d_in[6];
    float* out = (float*)d_out;

    // Clear accumulators (memset node in the captured graph)
    void* accPtr = nullptr;
    cudaGetSymbolAddress(&accPtr, g_acc);
    cudaMemsetAsync(accPtr, 0, sizeof(float) * (size_t)2 * BB * HW * 4, 0);

    int threads = 256;
    int blocks = (NPIX + threads - 1) / threads;
    splat_kernel<<<blocks, threads>>>(img0, img1, flow0, flow1, z0, z1);

    dim3 gblk(TBX, TTY, 1);
    dim3 ggrid(WW / TPX, HH / TTY, BB);
    open_compose_kernel<<<ggrid, gblk>>>(kptr, flow0, flow1, out);
}